// round 16
// baseline (speedup 1.0000x reference)
#include <cuda_runtime.h>
#include <cuda_bf16.h>
#include <math.h>
#include <stdint.h>

#define NROW 9216   // L*B = 576*16
#define NBLK 100    // persistent grid size (<=148 SMs -> co-resident, barrier safe)

// ---------------- static device scratch (no allocations) ----------------
__device__ __align__(16) float g_projF[576 * 3200 * 16];   // [t][gate][b]
__device__ __align__(16) float g_projB[576 * 3200 * 16];
__device__ __align__(16) float g_h0[NROW * 1600];          // [t*16+b][1600]
__device__ __align__(16) float g_h1[NROW * 1600];
__device__ __align__(16) float g_hbuf[2][2][12800];        // [parity][dir][u*16+b]
__device__ __align__(16) float g_logits[NROW * 60];
__device__ __align__(16) float g_srf[1728 * 16 * 3];
__device__ __align__(16) float g_frag[72 * 24 * 16 * 3];
__device__ __align__(16) float g_WT[4][800 * 3200];        // recurrent W, transposed

// pre-split bf16 hi/lo operand arrays for tensor-core GEMMs
__device__ __align__(16) __nv_bfloat16 g_xh[NROW * 64],  g_xl[NROW * 64];      // K padded 41->64
__device__ __align__(16) __nv_bfloat16 g_w0h[2][3200 * 64], g_w0l[2][3200 * 64];
__device__ __align__(16) __nv_bfloat16 g_h0h[NROW * 1600], g_h0l[NROW * 1600];
__device__ __align__(16) __nv_bfloat16 g_h1h[NROW * 1600], g_h1l[NROW * 1600];
__device__ __align__(16) __nv_bfloat16 g_w1h[2][3200 * 1600], g_w1l[2][3200 * 1600];
__device__ __align__(16) __nv_bfloat16 g_fch[60 * 1600], g_fcl[60 * 1600];

__device__ unsigned g_bar_count2[2];   // per-direction barriers
__device__ unsigned g_bar_phase2[2];

// ---------------- packed f32x2 helpers ----------------
__device__ __forceinline__ void fma2(unsigned long long& acc, unsigned long long a,
                                     unsigned long long b) {
    asm("fma.rn.f32x2 %0, %1, %2, %0;" : "+l"(acc) : "l"(a), "l"(b));
}
__device__ __forceinline__ unsigned long long bcast2(float x) {
    unsigned long long r;
    asm("mov.b64 %0, {%1, %1};" : "=l"(r) : "f"(x));
    return r;
}
__device__ __forceinline__ float2 unpack2(unsigned long long v) {
    float2 r;
    asm("mov.b64 {%0, %1}, %2;" : "=f"(r.x), "=f"(r.y) : "l"(v));
    return r;
}

// ---------------- acquire/release primitives ----------------
__device__ __forceinline__ unsigned atom_arrive_acqrel(unsigned* p) {
    unsigned old;
    asm volatile("atom.acq_rel.gpu.global.add.u32 %0, [%1], 1;"
                 : "=r"(old) : "l"(p) : "memory");
    return old;
}
__device__ __forceinline__ unsigned ld_acquire(const unsigned* p) {
    unsigned v;
    asm volatile("ld.acquire.gpu.global.u32 %0, [%1];" : "=r"(v) : "l"(p) : "memory");
    return v;
}
__device__ __forceinline__ unsigned ld_relaxed(const unsigned* p) {
    unsigned v;
    asm volatile("ld.relaxed.gpu.global.u32 %0, [%1];" : "=r"(v) : "l"(p) : "memory");
    return v;
}
__device__ __forceinline__ void st_release(unsigned* p, unsigned v) {
    asm volatile("st.release.gpu.global.u32 [%0], %1;" :: "l"(p), "r"(v) : "memory");
}
__device__ __forceinline__ void st_relaxed(unsigned* p, unsigned v) {
    asm volatile("st.relaxed.gpu.global.u32 [%0], %1;" :: "l"(p), "r"(v) : "memory");
}

// ---------------- fast activations ----------------
__device__ __forceinline__ float fast_tanh(float x) {
    float y;
    asm("tanh.approx.f32 %0, %1;" : "=f"(y) : "f"(x));
    return y;
}
__device__ __forceinline__ float fast_sig(float x) {
    return 0.5f * fast_tanh(0.5f * x) + 0.5f;
}

// ---------------- input assembly: one_hot++pssm, padded K=64, split hi/lo ----------------
__global__ void build_x_hl(const int* __restrict__ seq, const float* __restrict__ pssm) {
    int i = blockIdx.x * blockDim.x + threadIdx.x;
    if (i >= NROW * 64) return;
    int row = i >> 6, k = i & 63;
    float v = 0.f;
    if (k < 20)      v = (seq[row] == k) ? 1.0f : 0.0f;
    else if (k < 41) v = pssm[(size_t)row * 21 + (k - 20)];
    __nv_bfloat16 h = __float2bfloat16_rn(v);
    g_xh[i] = h;
    g_xl[i] = __float2bfloat16_rn(v - __bfloat162float(h));
}

// ---------------- pad+split layer-0 input weights (3200x41 -> 3200x64) ----------------
__global__ void pad_split_w0(const float* __restrict__ wf, const float* __restrict__ wb) {
    int i = blockIdx.x * blockDim.x + threadIdx.x;
    if (i >= 2 * 3200 * 64) return;
    int m = i / (3200 * 64);
    int o = i - m * (3200 * 64);
    int r = o >> 6, k = o & 63;
    const float* W = m ? wb : wf;
    float v = (k < 41) ? W[r * 41 + k] : 0.f;
    __nv_bfloat16 h = __float2bfloat16_rn(v);
    g_w0h[m][o] = h;
    g_w0l[m][o] = __float2bfloat16_rn(v - __bfloat162float(h));
}

// ---------------- generic fp32 -> bf16 hi/lo split (vectorized) ----------------
// sel 0: g_h0 -> g_h0h/l   1: g_h1 -> g_h1h/l
// sel 2: p -> g_w1h/l[0]   3: p -> g_w1h/l[1]   4: p -> g_fch/l
__global__ void split_sel(int sel, const float* __restrict__ p, int n4) {
    const float4* src;
    __nv_bfloat162 *hi, *lo;
    if (sel == 0)      { src = (const float4*)g_h0; hi = (__nv_bfloat162*)g_h0h; lo = (__nv_bfloat162*)g_h0l; }
    else if (sel == 1) { src = (const float4*)g_h1; hi = (__nv_bfloat162*)g_h1h; lo = (__nv_bfloat162*)g_h1l; }
    else if (sel == 2) { src = (const float4*)p; hi = (__nv_bfloat162*)g_w1h[0]; lo = (__nv_bfloat162*)g_w1l[0]; }
    else if (sel == 3) { src = (const float4*)p; hi = (__nv_bfloat162*)g_w1h[1]; lo = (__nv_bfloat162*)g_w1l[1]; }
    else               { src = (const float4*)p; hi = (__nv_bfloat162*)g_fch;    lo = (__nv_bfloat162*)g_fcl; }
    for (int i = blockIdx.x * blockDim.x + threadIdx.x; i < n4;
         i += gridDim.x * blockDim.x) {
        float4 v = src[i];
        __nv_bfloat16 h0 = __float2bfloat16_rn(v.x), h1 = __float2bfloat16_rn(v.y);
        __nv_bfloat16 h2 = __float2bfloat16_rn(v.z), h3 = __float2bfloat16_rn(v.w);
        hi[i * 2]     = __halves2bfloat162(h0, h1);
        hi[i * 2 + 1] = __halves2bfloat162(h2, h3);
        lo[i * 2]     = __halves2bfloat162(__float2bfloat16_rn(v.x - __bfloat162float(h0)),
                                           __float2bfloat16_rn(v.y - __bfloat162float(h1)));
        lo[i * 2 + 1] = __halves2bfloat162(__float2bfloat16_rn(v.z - __bfloat162float(h2)),
                                           __float2bfloat16_rn(v.w - __bfloat162float(h3)));
    }
}

// ---------------- Whh transpose into per-CTA coalesced layout ----------------
__global__ void transpose_whh(const float* __restrict__ w0, const float* __restrict__ w1,
                              const float* __restrict__ w2, const float* __restrict__ w3) {
    const float* Ws[4] = {w0, w1, w2, w3};
    const int per = 800 * 3200;
    int total = 4 * per;
    for (int i = blockIdx.x * blockDim.x + threadIdx.x; i < total;
         i += gridDim.x * blockDim.x) {
        int m = i / per;
        int o = i - m * per;
        int k = o / 3200;
        int idx = o - k * 3200;
        int gblk = idx >> 6;
        int gate = (idx >> 4) & 3;
        int ul = idx & 15;
        int r = gate * 800 + gblk * 16 + ul;
        g_WT[m][o] = Ws[m][(size_t)r * 800 + k];
    }
}

// ---------------- split-bf16 tensor-core GEMM, pre-split operands ----------------
// C[m][n] = sum_k (Ah+Al)[m][k]*(Bh+Bl)[n][k] + bias  (Al*Bl dropped)
// CTA 128(M) x 64(N), BK=64, 8 warps of 32x32. K%64==0, M%128==0.
#define TPITCH 72   // bf16 units per smem row (144B) -> conflict-free ldmatrix

__device__ __forceinline__ void ldmx4(uint32_t& r0, uint32_t& r1, uint32_t& r2,
                                      uint32_t& r3, uint32_t addr) {
    asm volatile("ldmatrix.sync.aligned.m8n8.x4.shared.b16 {%0,%1,%2,%3}, [%4];"
                 : "=r"(r0), "=r"(r1), "=r"(r2), "=r"(r3) : "r"(addr));
}
__device__ __forceinline__ void mma16816(float* d, const uint32_t* a, const uint32_t* b) {
    asm volatile(
        "mma.sync.aligned.m16n8k16.row.col.f32.bf16.bf16.f32 "
        "{%0,%1,%2,%3}, {%4,%5,%6,%7}, {%8,%9}, {%0,%1,%2,%3};"
        : "+f"(d[0]), "+f"(d[1]), "+f"(d[2]), "+f"(d[3])
        : "r"(a[0]), "r"(a[1]), "r"(a[2]), "r"(a[3]), "r"(b[0]), "r"(b[1]));
}

// smem map (bytes): sAh@0 (18432) sAl@18432 sBh@36864 (9216) sBl@46080; total 55296
__global__ void __launch_bounds__(256) tgemm_hl(
    int Asel, int Bsel, const float* __restrict__ bias1, const float* __restrict__ bias2,
    int Csel, int M, int N, int K, int mode)
{
    extern __shared__ __align__(16) char smraw[];
    float* stage = reinterpret_cast<float*>(smraw);

    const __nv_bfloat16 *Ah, *Al;
    if (Asel == 0)      { Ah = g_xh;  Al = g_xl;  }
    else if (Asel == 1) { Ah = g_h0h; Al = g_h0l; }
    else                { Ah = g_h1h; Al = g_h1l; }
    const __nv_bfloat16 *Bh_g, *Bl_g;
    if (Bsel == 0)      { Bh_g = g_w0h[0]; Bl_g = g_w0l[0]; }
    else if (Bsel == 1) { Bh_g = g_w0h[1]; Bl_g = g_w0l[1]; }
    else if (Bsel == 2) { Bh_g = g_w1h[0]; Bl_g = g_w1l[0]; }
    else if (Bsel == 3) { Bh_g = g_w1h[1]; Bl_g = g_w1l[1]; }
    else                { Bh_g = g_fch;    Bl_g = g_fcl;    }
    float* C = (Csel == 0) ? g_projF : ((Csel == 1) ? g_projB : g_logits);

    int tid = threadIdx.x;
    int lane = tid & 31;
    int w = tid >> 5;
    int wm = (w >> 1) * 32;
    int wn = (w & 1) * 32;
    int mB = blockIdx.y * 128, nB = blockIdx.x * 64;

    uint32_t smb = (uint32_t)__cvta_generic_to_shared(smraw);
    int a_row = (lane & 15);
    int a_col = (lane >> 4) << 3;
    int b_row = (lane & 7) + ((lane >> 4) << 3);
    int b_col = ((lane >> 3) & 1) << 3;

    float acc[2][4][4];
#pragma unroll
    for (int mt = 0; mt < 2; mt++)
#pragma unroll
        for (int nt = 0; nt < 4; nt++)
#pragma unroll
            for (int e = 0; e < 4; e++) acc[mt][nt][e] = 0.0f;

    for (int k0 = 0; k0 < K; k0 += 64) {
        __syncthreads();
        // A: 128 rows x 64 k, hi+lo, 16B chunks
#pragma unroll
        for (int e = 0; e < 4; e++) {
            int fid = tid + e * 256;
            int row = fid >> 3;
            int q = fid & 7;
            int so = (row * TPITCH + q * 8) * 2;
            *reinterpret_cast<uint4*>(smraw + so) =
                *(reinterpret_cast<const uint4*>(Ah + (size_t)(mB + row) * K + k0) + q);
            *reinterpret_cast<uint4*>(smraw + 18432 + so) =
                *(reinterpret_cast<const uint4*>(Al + (size_t)(mB + row) * K + k0) + q);
        }
        // B: 64 rows x 64 k (row guard)
#pragma unroll
        for (int e = 0; e < 2; e++) {
            int fid = tid + e * 256;
            int row = fid >> 3;
            int q = fid & 7;
            uint4 vh = make_uint4(0u, 0u, 0u, 0u), vl = make_uint4(0u, 0u, 0u, 0u);
            if (nB + row < N) {
                vh = *(reinterpret_cast<const uint4*>(Bh_g + (size_t)(nB + row) * K + k0) + q);
                vl = *(reinterpret_cast<const uint4*>(Bl_g + (size_t)(nB + row) * K + k0) + q);
            }
            int so = (row * TPITCH + q * 8) * 2;
            *reinterpret_cast<uint4*>(smraw + 36864 + so) = vh;
            *reinterpret_cast<uint4*>(smraw + 46080 + so) = vl;
        }
        __syncthreads();

#pragma unroll
        for (int kk = 0; kk < 64; kk += 16) {
            uint32_t Ah0[4], Ah1[4], Al0[4], Al1[4];
            uint32_t Bh[2][4], Bl[2][4];
            uint32_t a0 = smb + ((wm + a_row) * TPITCH + kk + a_col) * 2;
            ldmx4(Ah0[0], Ah0[1], Ah0[2], Ah0[3], a0);
            uint32_t a1 = smb + ((wm + 16 + a_row) * TPITCH + kk + a_col) * 2;
            ldmx4(Ah1[0], Ah1[1], Ah1[2], Ah1[3], a1);
            ldmx4(Al0[0], Al0[1], Al0[2], Al0[3], a0 + 18432);
            ldmx4(Al1[0], Al1[1], Al1[2], Al1[3], a1 + 18432);
#pragma unroll
            for (int p = 0; p < 2; p++) {
                uint32_t bo = smb + 36864 +
                    ((wn + p * 16 + b_row) * TPITCH + kk + b_col) * 2;
                ldmx4(Bh[p][0], Bh[p][1], Bh[p][2], Bh[p][3], bo);
                ldmx4(Bl[p][0], Bl[p][1], Bl[p][2], Bl[p][3], bo + 9216);
            }
#pragma unroll
            for (int nt = 0; nt < 4; nt++) {
                const uint32_t* bh = &Bh[nt >> 1][(nt & 1) * 2];
                const uint32_t* bl = &Bl[nt >> 1][(nt & 1) * 2];
                mma16816(acc[0][nt], Ah0, bh);
                mma16816(acc[1][nt], Ah1, bh);
                mma16816(acc[0][nt], Ah0, bl);
                mma16816(acc[1][nt], Ah1, bl);
                mma16816(acc[0][nt], Al0, bh);
                mma16816(acc[1][nt], Al1, bh);
            }
        }
    }

    // biases
#pragma unroll
    for (int nt = 0; nt < 4; nt++) {
        int n0 = nB + wn + nt * 8 + (lane & 3) * 2;
        float bv0 = 0.f, bv1 = 0.f;
        if (n0 < N)     { bv0 = bias1[n0];     if (bias2) bv0 += bias2[n0]; }
        if (n0 + 1 < N) { bv1 = bias1[n0 + 1]; if (bias2) bv1 += bias2[n0 + 1]; }
#pragma unroll
        for (int mt = 0; mt < 2; mt++) {
            acc[mt][nt][0] += bv0; acc[mt][nt][1] += bv1;
            acc[mt][nt][2] += bv0; acc[mt][nt][3] += bv1;
        }
    }

    if (mode == 0) {
#pragma unroll
        for (int mt = 0; mt < 2; mt++)
#pragma unroll
            for (int nt = 0; nt < 4; nt++) {
                int m = mB + wm + mt * 16 + (lane >> 2);
                int n0 = nB + wn + nt * 8 + (lane & 3) * 2;
                if (n0 < N)     C[(size_t)m * N + n0]           = acc[mt][nt][0];
                if (n0 + 1 < N) C[(size_t)m * N + n0 + 1]       = acc[mt][nt][1];
                if (n0 < N)     C[(size_t)(m + 8) * N + n0]     = acc[mt][nt][2];
                if (n0 + 1 < N) C[(size_t)(m + 8) * N + n0 + 1] = acc[mt][nt][3];
            }
        return;
    }

    // mode 1: [m>>4][n][m&15] layout via smem transpose + coalesced float4 stores
    __syncthreads();
    float* st = stage + w * 1056;     // 32(nl) x 33(ml)
#pragma unroll
    for (int mt = 0; mt < 2; mt++)
#pragma unroll
        for (int nt = 0; nt < 4; nt++) {
            int ml = mt * 16 + (lane >> 2);
            int nl = nt * 8 + (lane & 3) * 2;
            st[nl * 33 + ml]           = acc[mt][nt][0];
            st[(nl + 1) * 33 + ml]     = acc[mt][nt][1];
            st[nl * 33 + ml + 8]       = acc[mt][nt][2];
            st[(nl + 1) * 33 + ml + 8] = acc[mt][nt][3];
        }
    __syncwarp();
#pragma unroll
    for (int i = 0; i < 8; i++) {
        int t2 = i >> 2;
        int nl = (i & 3) * 8 + (lane >> 2);
        int bq = lane & 3;
        float4 v;
        v.x = st[nl * 33 + t2 * 16 + bq * 4 + 0];
        v.y = st[nl * 33 + t2 * 16 + bq * 4 + 1];
        v.z = st[nl * 33 + t2 * 16 + bq * 4 + 2];
        v.w = st[nl * 33 + t2 * 16 + bq * 4 + 3];
        int t = (mB + wm) / 16 + t2;
        int gn = nB + wn + nl;
        *reinterpret_cast<float4*>(&C[((size_t)t * N + gn) * 16 + bq * 4]) = v;
    }
}

// ---------------- persistent bi-LSTM layer ----------------
// 100 CTAs: dir = bx&1, gblk = bx>>1. Per-direction grid barrier (50 arrivals).
// W: ks<3 -> __ldca (L1-resident, ~154KB of ~160KB L1), ks==3 -> __ldcg;
// prefetch one 8-group ahead to hide L2 latency. gsm aliases red[0..1023].
__global__ void __launch_bounds__(256, 1) lstm_layer(int layer)
{
    extern __shared__ float smem[];
    float* hs   = smem;           // 12800 floats
    float* red  = smem + 12800;   // 4096 floats; red[0..1023] doubles as gsm
    float* gsm  = red;

    int bx = blockIdx.x;
    int dir = bx & 1, gblk = bx >> 1;
    int tid = threadIdx.x;
    const float* proj = dir ? g_projB : g_projF;
    const float* WT   = g_WT[layer * 2 + dir];
    float* hseq = layer ? g_h1 : g_h0;

    unsigned my_phase = 0;
    if (tid == 0) my_phase = ld_relaxed(&g_bar_phase2[dir]);

    int ua = tid >> 4, b = tid & 15;
    int u  = gblk * 16 + ua;
    int w  = tid >> 5, lane = tid & 31;
    int ks = w & 3;
    int rh = w >> 2;
    int row_local = rh * 32 + lane;
    const float* Wk = WT + (size_t)(ks * 200) * 3200 + gblk * 64 + row_local;
    bool useca = (ks < 3);
    int rrow = tid >> 2, bq = tid & 3;
    int Rglob = (rrow >> 4) * 800 + gblk * 16 + (rrow & 15);

    const ulonglong2* hs2 = reinterpret_cast<const ulonglong2*>(hs);

    float c_reg = 0.0f;

    for (int s = 0; s <= 576; s++) {
        if (s > 0) {
            float gi = gsm[(0 * 16 + ua) * 16 + b];
            float gf = gsm[(16 + ua) * 16 + b];
            float gg = gsm[(32 + ua) * 16 + b];
            float go = gsm[(48 + ua) * 16 + b];
            float cn = fast_sig(gf) * c_reg + fast_sig(gi) * fast_tanh(gg);
            c_reg = cn;
            float h = fast_sig(go) * fast_tanh(cn);
            __stcg(&g_hbuf[(s - 1) & 1][dir][u * 16 + b], h);
            int tprev = dir ? (576 - s) : (s - 1);
            __stcg(&hseq[(size_t)(tprev * 16 + b) * 1600 + dir * 800 + u], h);
        }
        if (s == 576) break;

        // per-direction flush-free grid barrier
        __syncthreads();
        if (tid == 0) {
            my_phase++;
            unsigned a = atom_arrive_acqrel(&g_bar_count2[dir]);
            if (a == 49u) {
                st_relaxed(&g_bar_count2[dir], 0u);
                st_release(&g_bar_phase2[dir], my_phase);
            } else {
                while (ld_acquire(&g_bar_phase2[dir]) != my_phase) { }
            }
        }
        __syncthreads();

        if (s == 0) {
            for (int e4 = tid; e4 < 3200; e4 += 256)
                reinterpret_cast<float4*>(hs)[e4] = make_float4(0.f, 0.f, 0.f, 0.f);
        } else {
            const float4* hb = reinterpret_cast<const float4*>(g_hbuf[(s - 1) & 1][dir]);
            for (int e4 = tid; e4 < 3200; e4 += 256)
                reinterpret_cast<float4*>(hs)[e4] = __ldcg(hb + e4);
        }
        __syncthreads();

        // matmul with W prefetch (1 group lookahead)
        unsigned long long acc0 = 0ull, acc1 = 0ull, acc2 = 0ull, acc3 = 0ull;
        unsigned long long acc4 = 0ull, acc5 = 0ull, acc6 = 0ull, acc7 = 0ull;
        int kbase = ks * 200;
        float wv[8];
#pragma unroll
        for (int j = 0; j < 8; j++)
            wv[j] = useca ? __ldca(Wk + (size_t)j * 3200) : __ldcg(Wk + (size_t)j * 3200);
#pragma unroll 1
        for (int kk = 0; kk < 200; kk += 8) {
            float wn[8];
            int kn = kk + 8;
            if (kn < 200) {
#pragma unroll
                for (int j = 0; j < 8; j++)
                    wn[j] = useca ? __ldca(Wk + (size_t)(kn + j) * 3200)
                                  : __ldcg(Wk + (size_t)(kn + j) * 3200);
            } else {
#pragma unroll
                for (int j = 0; j < 8; j++) wn[j] = 0.f;
            }
#pragma unroll
            for (int j = 0; j < 8; j++) {
                int k = kbase + kk + j;
                ulonglong2 hA = hs2[k * 4 + 0];
                ulonglong2 hB = hs2[k * 4 + 1];
                ulonglong2 hC = hs2[k * 4 + 2];
                ulonglong2 hD = hs2[k * 4 + 3];
                unsigned long long wp = bcast2(wv[j]);
                fma2(acc0, wp, hA.x); fma2(acc1, wp, hA.y);
                fma2(acc2, wp, hB.x); fma2(acc3, wp, hB.y);
                fma2(acc4, wp, hC.x); fma2(acc5, wp, hC.y);
                fma2(acc6, wp, hD.x); fma2(acc7, wp, hD.y);
            }
#pragma unroll
            for (int j = 0; j < 8; j++) wv[j] = wn[j];
        }
        {
            float* dst = red + ks * 1024 + row_local * 16;
            float2 p0 = unpack2(acc0), p1 = unpack2(acc1);
            float2 p2 = unpack2(acc2), p3 = unpack2(acc3);
            float2 p4 = unpack2(acc4), p5 = unpack2(acc5);
            float2 p6 = unpack2(acc6), p7 = unpack2(acc7);
            *reinterpret_cast<float4*>(dst + 0)  = make_float4(p0.x, p0.y, p1.x, p1.y);
            *reinterpret_cast<float4*>(dst + 4)  = make_float4(p2.x, p2.y, p3.x, p3.y);
            *reinterpret_cast<float4*>(dst + 8)  = make_float4(p4.x, p4.y, p5.x, p5.y);
            *reinterpret_cast<float4*>(dst + 12) = make_float4(p6.x, p6.y, p7.x, p7.y);
        }
        __syncthreads();
        {
            int t = dir ? (575 - s) : s;
            float4 pv = __ldcg(reinterpret_cast<const float4*>(
                            proj + ((size_t)t * 3200 + Rglob) * 16 + bq * 4));
            int off = rrow * 16 + bq * 4;
            float4 s0 = *reinterpret_cast<const float4*>(red + 0 * 1024 + off);
            float4 s1 = *reinterpret_cast<const float4*>(red + 1 * 1024 + off);
            float4 s2 = *reinterpret_cast<const float4*>(red + 2 * 1024 + off);
            float4 s3 = *reinterpret_cast<const float4*>(red + 3 * 1024 + off);
            float4 rv;
            rv.x = pv.x + ((s0.x + s1.x) + (s2.x + s3.x));
            rv.y = pv.y + ((s0.y + s1.y) + (s2.y + s3.y));
            rv.z = pv.z + ((s0.z + s1.z) + (s2.z + s3.z));
            rv.w = pv.w + ((s0.w + s1.w) + (s2.w + s3.w));
            *reinterpret_cast<float4*>(gsm + off) = rv;   // in-place into red[0] slab
        }
        __syncthreads();
    }
}

// ---------------- softmax + angle mixing + SRF ----------------
__global__ void phisrf(const float* __restrict__ alphabet,
                       const float* __restrict__ blen, const float* __restrict__ bang) {
    __shared__ float sA[180], cA[180];
    int tid = threadIdx.x;
    if (tid < 180) { float a = alphabet[tid]; sA[tid] = sinf(a); cA[tid] = cosf(a); }
    __syncthreads();
    int row = blockIdx.x * 256 + tid;
    if (row >= NROW) return;
    const float* z = g_logits + (size_t)row * 60;
    float mx = -1e30f;
    for (int j = 0; j < 60; j++) mx = fmaxf(mx, z[j]);
    float ss0 = 0, ss1 = 0, ss2 = 0, sc0 = 0, sc1 = 0, sc2 = 0;
    for (int j = 0; j < 60; j++) {
        float e = __expf(z[j] - mx);
        ss0 += e * sA[j * 3 + 0]; sc0 += e * cA[j * 3 + 0];
        ss1 += e * sA[j * 3 + 1]; sc1 += e * cA[j * 3 + 1];
        ss2 += e * sA[j * 3 + 2]; sc2 += e * cA[j * 3 + 2];
    }
    float ss[3] = {ss0, ss1, ss2}, sc[3] = {sc0, sc1, sc2};
    int l = row >> 4, b = row & 15;
#pragma unroll
    for (int d = 0; d < 3; d++) {
        float rh = rsqrtf(ss[d] * ss[d] + sc[d] * sc[d]);
        float cp = sc[d] * rh, sp = ss[d] * rh;
        float rr = blen[d], th = bang[d];
        float sth = sinf(th), cth = cosf(th);
        float* o = &g_srf[(((size_t)(3 * l + d)) * 16 + b) * 3];
        o[0] = rr * cth;
        o[1] = rr * cp * sth;
        o[2] = rr * sp * sth;
    }
}

// ---------------- pNeRF ----------------
struct F3 { float x, y, z; };
__device__ __forceinline__ F3 mk3(float x, float y, float z) { F3 r; r.x = x; r.y = y; r.z = z; return r; }
__device__ __forceinline__ F3 sub3(F3 a, F3 b) { return mk3(a.x - b.x, a.y - b.y, a.z - b.z); }
__device__ __forceinline__ F3 crs3(F3 a, F3 b) {
    return mk3(a.y * b.z - a.z * b.y, a.z * b.x - a.x * b.z, a.x * b.y - a.y * b.x);
}
__device__ __forceinline__ F3 unit3(F3 v) {
    float r = rsqrtf(v.x * v.x + v.y * v.y + v.z * v.z);
    return mk3(v.x * r, v.y * r, v.z * r);
}

__global__ void pnerf_kernel(float* __restrict__ out) {
    __shared__ float Rm[16][9];
    __shared__ float Og[16][3];
    int tid = threadIdx.x;
    {
        int kf = tid >> 4, b = tid & 15;
        F3 A  = mk3(-0.70710678118654752f, 1.22474487139158905f, 0.f);
        F3 Bp = mk3(-1.41421356237309505f, 0.f, 0.f);
        F3 C  = mk3(0.f, 0.f, 0.f);
        for (int f = 0; f < 72; f++) {
            const float* ct = &g_srf[(((size_t)(kf * 72 + f)) * 16 + b) * 3];
            F3 bc = unit3(sub3(C, Bp));
            F3 n  = unit3(crs3(sub3(Bp, A), bc));
            F3 m  = crs3(n, bc);
            F3 D  = mk3(C.x + bc.x * ct[0] + m.x * ct[1] + n.x * ct[2],
                        C.y + bc.y * ct[0] + m.y * ct[1] + n.y * ct[2],
                        C.z + bc.z * ct[0] + m.z * ct[1] + n.z * ct[2]);
            float* fp = &g_frag[((((size_t)f) * 24 + kf) * 16 + b) * 3];
            fp[0] = D.x; fp[1] = D.y; fp[2] = D.z;
            A = Bp; Bp = C; C = D;
        }
    }
    __syncthreads();
    for (int e = tid; e < 72 * 16; e += 384) {
        int f = e >> 4, b = e & 15;
        const float* fp = &g_frag[((((size_t)f) * 24 + 0) * 16 + b) * 3];
        float* o = &out[((size_t)f * 16 + b) * 3];
        o[0] = fp[0]; o[1] = fp[1]; o[2] = fp[2];
    }
    __syncthreads();
    for (int k = 1; k < 24; k++) {
        if (tid < 16) {
            int base = 72 * k;
            const float* pa = &out[((size_t)(base - 3) * 16 + tid) * 3];
            const float* pb = &out[((size_t)(base - 2) * 16 + tid) * 3];
            const float* pc = &out[((size_t)(base - 1) * 16 + tid) * 3];
            F3 A  = mk3(pa[0], pa[1], pa[2]);
            F3 B2 = mk3(pb[0], pb[1], pb[2]);
            F3 C  = mk3(pc[0], pc[1], pc[2]);
            F3 bc = unit3(sub3(C, B2));
            F3 n  = unit3(crs3(sub3(B2, A), bc));
            F3 m  = crs3(n, bc);
            Rm[tid][0] = bc.x; Rm[tid][1] = bc.y; Rm[tid][2] = bc.z;
            Rm[tid][3] = m.x;  Rm[tid][4] = m.y;  Rm[tid][5] = m.z;
            Rm[tid][6] = n.x;  Rm[tid][7] = n.y;  Rm[tid][8] = n.z;
            Og[tid][0] = C.x;  Og[tid][1] = C.y;  Og[tid][2] = C.z;
        }
        __syncthreads();
        for (int e = tid; e < 72 * 16; e += 384) {
            int f = e >> 4, b = e & 15;
            const float* fp = &g_frag[((((size_t)f) * 24 + k) * 16 + b) * 3];
            float vx = fp[0], vy = fp[1], vz = fp[2];
            float* o = &out[((size_t)(72 * k + f) * 16 + b) * 3];
            o[0] = Og[b][0] + Rm[b][0] * vx + Rm[b][3] * vy + Rm[b][6] * vz;
            o[1] = Og[b][1] + Rm[b][1] * vx + Rm[b][4] * vy + Rm[b][7] * vz;
            o[2] = Og[b][2] + Rm[b][2] * vx + Rm[b][5] * vy + Rm[b][8] * vz;
        }
        __syncthreads();
    }
}

// ---------------- launch ----------------
extern "C" void kernel_launch(void* const* d_in, const int* in_sizes, int n_in,
                              void* d_out, int out_size) {
    const int*   seq      = (const int*)  d_in[0];
    const float* pssm     = (const float*)d_in[1];
    const float* w_ih_l0f = (const float*)d_in[3];
    const float* w_hh_l0f = (const float*)d_in[4];
    const float* b_ih_l0f = (const float*)d_in[5];
    const float* b_hh_l0f = (const float*)d_in[6];
    const float* w_ih_l0b = (const float*)d_in[7];
    const float* w_hh_l0b = (const float*)d_in[8];
    const float* b_ih_l0b = (const float*)d_in[9];
    const float* b_hh_l0b = (const float*)d_in[10];
    const float* w_ih_l1f = (const float*)d_in[11];
    const float* w_hh_l1f = (const float*)d_in[12];
    const float* b_ih_l1f = (const float*)d_in[13];
    const float* b_hh_l1f = (const float*)d_in[14];
    const float* w_ih_l1b = (const float*)d_in[15];
    const float* w_hh_l1b = (const float*)d_in[16];
    const float* b_ih_l1b = (const float*)d_in[17];
    const float* b_hh_l1b = (const float*)d_in[18];
    const float* fc_w     = (const float*)d_in[19];
    const float* fc_b     = (const float*)d_in[20];
    const float* alphabet = (const float*)d_in[21];
    const float* blen     = (const float*)d_in[22];
    const float* bang     = (const float*)d_in[23];
    float* out = (float*)d_out;

    cudaFuncSetAttribute((const void*)lstm_layer,
                         cudaFuncAttributeMaxDynamicSharedMemorySize, 67584);
    cudaFuncSetAttribute((const void*)tgemm_hl,
                         cudaFuncAttributeMaxDynamicSharedMemorySize, 55296);

    // input prep (independent of LSTM outputs)
    build_x_hl<<<(NROW * 64 + 255) / 256, 256>>>(seq, pssm);
    pad_split_w0<<<(2 * 3200 * 64 + 255) / 256, 256>>>(w_ih_l0f, w_ih_l0b);
    split_sel<<<5000, 256>>>(2, w_ih_l1f, 3200 * 1600 / 4);
    split_sel<<<5000, 256>>>(3, w_ih_l1b, 3200 * 1600 / 4);
    split_sel<<<94, 256>>>(4, fc_w, 60 * 1600 / 4);
    transpose_whh<<<8192, 256>>>(w_hh_l0f, w_hh_l0b, w_hh_l1f, w_hh_l1b);

    // layer 0 projections (K padded to 64), tensor cores
    dim3 gT(50, 72);
    tgemm_hl<<<gT, 256, 55296>>>(0, 0, b_ih_l0f, b_hh_l0f, 0, NROW, 3200, 64, 1);
    tgemm_hl<<<gT, 256, 55296>>>(0, 1, b_ih_l0b, b_hh_l0b, 1, NROW, 3200, 64, 1);
    lstm_layer<<<NBLK, 256, 67584>>>(0);

    // split h0, then layer 1 projections (K=1600)
    split_sel<<<14400, 256>>>(0, nullptr, NROW * 1600 / 4);
    tgemm_hl<<<gT, 256, 55296>>>(1, 2, b_ih_l1f, b_hh_l1f, 0, NROW, 3200, 1600, 1);
    tgemm_hl<<<gT, 256, 55296>>>(1, 3, b_ih_l1b, b_hh_l1b, 1, NROW, 3200, 1600, 1);
    lstm_layer<<<NBLK, 256, 67584>>>(1);

    // split h1, FC -> logits
    split_sel<<<14400, 256>>>(1, nullptr, NROW * 1600 / 4);
    tgemm_hl<<<dim3(1, 72), 256, 55296>>>(2, 4, fc_b, nullptr, 2, NROW, 60, 1600, 0);

    phisrf<<<36, 256>>>(alphabet, blen, bang);
    pnerf_kernel<<<1, 384>>>(out);
}

// round 17
// speedup vs baseline: 1.1553x; 1.1553x over previous
#include <cuda_runtime.h>
#include <cuda_bf16.h>
#include <math.h>
#include <stdint.h>

#define NROW 9216   // L*B = 576*16
#define NBLK 100    // persistent grid size (<=148 SMs -> co-resident, barrier safe)

// ---------------- static device scratch (no allocations) ----------------
__device__ __align__(16) float g_projF[576 * 3200 * 16];   // [t][gate][b]
__device__ __align__(16) float g_projB[576 * 3200 * 16];
__device__ __align__(16) float g_h0[NROW * 1600];          // [t*16+b][1600]
__device__ __align__(16) float g_h1[NROW * 1600];
__device__ __align__(16) float g_hbuf[2][2][12800];        // [parity][dir][u*16+b]
__device__ __align__(16) float g_logits[NROW * 60];
__device__ __align__(16) float g_srf[1728 * 16 * 3];
__device__ __align__(16) float g_frag[72 * 24 * 16 * 3];
__device__ __align__(16) float g_WT[4][800 * 3200];        // recurrent W, transposed

// pre-split bf16 hi/lo operand arrays for tensor-core GEMMs
__device__ __align__(16) __nv_bfloat16 g_xh[NROW * 64],  g_xl[NROW * 64];      // K padded 41->64
__device__ __align__(16) __nv_bfloat16 g_w0h[2][3200 * 64], g_w0l[2][3200 * 64];
__device__ __align__(16) __nv_bfloat16 g_h0h[NROW * 1600], g_h0l[NROW * 1600];
__device__ __align__(16) __nv_bfloat16 g_h1h[NROW * 1600], g_h1l[NROW * 1600];
__device__ __align__(16) __nv_bfloat16 g_w1h[2][3200 * 1600], g_w1l[2][3200 * 1600];
__device__ __align__(16) __nv_bfloat16 g_fch[60 * 1600], g_fcl[60 * 1600];

__device__ unsigned g_bar_count;   // zero-init; returns to 0 after every barrier
__device__ unsigned g_bar_phase;   // monotone across replays (equality-tested)

// ---------------- packed f32x2 helpers ----------------
__device__ __forceinline__ void fma2(unsigned long long& acc, unsigned long long a,
                                     unsigned long long b) {
    asm("fma.rn.f32x2 %0, %1, %2, %0;" : "+l"(acc) : "l"(a), "l"(b));
}
__device__ __forceinline__ unsigned long long bcast2(float x) {
    unsigned long long r;
    asm("mov.b64 %0, {%1, %1};" : "=l"(r) : "f"(x));
    return r;
}
__device__ __forceinline__ float2 unpack2(unsigned long long v) {
    float2 r;
    asm("mov.b64 {%0, %1}, %2;" : "=f"(r.x), "=f"(r.y) : "l"(v));
    return r;
}

// ---------------- acquire/release primitives ----------------
__device__ __forceinline__ unsigned atom_arrive_acqrel(unsigned* p) {
    unsigned old;
    asm volatile("atom.acq_rel.gpu.global.add.u32 %0, [%1], 1;"
                 : "=r"(old) : "l"(p) : "memory");
    return old;
}
__device__ __forceinline__ unsigned ld_acquire(const unsigned* p) {
    unsigned v;
    asm volatile("ld.acquire.gpu.global.u32 %0, [%1];" : "=r"(v) : "l"(p) : "memory");
    return v;
}
__device__ __forceinline__ unsigned ld_relaxed(const unsigned* p) {
    unsigned v;
    asm volatile("ld.relaxed.gpu.global.u32 %0, [%1];" : "=r"(v) : "l"(p) : "memory");
    return v;
}
__device__ __forceinline__ void st_release(unsigned* p, unsigned v) {
    asm volatile("st.release.gpu.global.u32 [%0], %1;" :: "l"(p), "r"(v) : "memory");
}
__device__ __forceinline__ void st_relaxed(unsigned* p, unsigned v) {
    asm volatile("st.relaxed.gpu.global.u32 [%0], %1;" :: "l"(p), "r"(v) : "memory");
}

// ---------------- fast activations ----------------
__device__ __forceinline__ float fast_tanh(float x) {
    float y;
    asm("tanh.approx.f32 %0, %1;" : "=f"(y) : "f"(x));
    return y;
}
__device__ __forceinline__ float fast_sig(float x) {
    return 0.5f * fast_tanh(0.5f * x) + 0.5f;
}

// ---------------- input assembly: one_hot++pssm, padded K=64, split hi/lo ----------------
__global__ void build_x_hl(const int* __restrict__ seq, const float* __restrict__ pssm) {
    int i = blockIdx.x * blockDim.x + threadIdx.x;
    if (i >= NROW * 64) return;
    int row = i >> 6, k = i & 63;
    float v = 0.f;
    if (k < 20)      v = (seq[row] == k) ? 1.0f : 0.0f;
    else if (k < 41) v = pssm[(size_t)row * 21 + (k - 20)];
    __nv_bfloat16 h = __float2bfloat16_rn(v);
    g_xh[i] = h;
    g_xl[i] = __float2bfloat16_rn(v - __bfloat162float(h));
}

// ---------------- pad+split layer-0 input weights (3200x41 -> 3200x64) ----------------
__global__ void pad_split_w0(const float* __restrict__ wf, const float* __restrict__ wb) {
    int i = blockIdx.x * blockDim.x + threadIdx.x;
    if (i >= 2 * 3200 * 64) return;
    int m = i / (3200 * 64);
    int o = i - m * (3200 * 64);
    int r = o >> 6, k = o & 63;
    const float* W = m ? wb : wf;
    float v = (k < 41) ? W[r * 41 + k] : 0.f;
    __nv_bfloat16 h = __float2bfloat16_rn(v);
    g_w0h[m][o] = h;
    g_w0l[m][o] = __float2bfloat16_rn(v - __bfloat162float(h));
}

// ---------------- generic fp32 -> bf16 hi/lo split (vectorized) ----------------
// sel 0: g_h0 -> g_h0h/l   1: g_h1 -> g_h1h/l
// sel 2: p -> g_w1h/l[0]   3: p -> g_w1h/l[1]   4: p -> g_fch/l
__global__ void split_sel(int sel, const float* __restrict__ p, int n4) {
    const float4* src;
    __nv_bfloat162 *hi, *lo;
    if (sel == 0)      { src = (const float4*)g_h0; hi = (__nv_bfloat162*)g_h0h; lo = (__nv_bfloat162*)g_h0l; }
    else if (sel == 1) { src = (const float4*)g_h1; hi = (__nv_bfloat162*)g_h1h; lo = (__nv_bfloat162*)g_h1l; }
    else if (sel == 2) { src = (const float4*)p; hi = (__nv_bfloat162*)g_w1h[0]; lo = (__nv_bfloat162*)g_w1l[0]; }
    else if (sel == 3) { src = (const float4*)p; hi = (__nv_bfloat162*)g_w1h[1]; lo = (__nv_bfloat162*)g_w1l[1]; }
    else               { src = (const float4*)p; hi = (__nv_bfloat162*)g_fch;    lo = (__nv_bfloat162*)g_fcl; }
    for (int i = blockIdx.x * blockDim.x + threadIdx.x; i < n4;
         i += gridDim.x * blockDim.x) {
        float4 v = src[i];
        __nv_bfloat16 h0 = __float2bfloat16_rn(v.x), h1 = __float2bfloat16_rn(v.y);
        __nv_bfloat16 h2 = __float2bfloat16_rn(v.z), h3 = __float2bfloat16_rn(v.w);
        hi[i * 2]     = __halves2bfloat162(h0, h1);
        hi[i * 2 + 1] = __halves2bfloat162(h2, h3);
        lo[i * 2]     = __halves2bfloat162(__float2bfloat16_rn(v.x - __bfloat162float(h0)),
                                           __float2bfloat16_rn(v.y - __bfloat162float(h1)));
        lo[i * 2 + 1] = __halves2bfloat162(__float2bfloat16_rn(v.z - __bfloat162float(h2)),
                                           __float2bfloat16_rn(v.w - __bfloat162float(h3)));
    }
}

// ---------------- Whh transpose into per-CTA coalesced layout ----------------
__global__ void transpose_whh(const float* __restrict__ w0, const float* __restrict__ w1,
                              const float* __restrict__ w2, const float* __restrict__ w3) {
    const float* Ws[4] = {w0, w1, w2, w3};
    const int per = 800 * 3200;
    int total = 4 * per;
    for (int i = blockIdx.x * blockDim.x + threadIdx.x; i < total;
         i += gridDim.x * blockDim.x) {
        int m = i / per;
        int o = i - m * per;
        int k = o / 3200;
        int idx = o - k * 3200;
        int gblk = idx >> 6;
        int gate = (idx >> 4) & 3;
        int ul = idx & 15;
        int r = gate * 800 + gblk * 16 + ul;
        g_WT[m][o] = Ws[m][(size_t)r * 800 + k];
    }
}

// ---------------- split-bf16 tensor-core GEMM, pre-split operands ----------------
#define TPITCH 72   // bf16 units per smem row (144B) -> conflict-free ldmatrix

__device__ __forceinline__ void ldmx4(uint32_t& r0, uint32_t& r1, uint32_t& r2,
                                      uint32_t& r3, uint32_t addr) {
    asm volatile("ldmatrix.sync.aligned.m8n8.x4.shared.b16 {%0,%1,%2,%3}, [%4];"
                 : "=r"(r0), "=r"(r1), "=r"(r2), "=r"(r3) : "r"(addr));
}
__device__ __forceinline__ void mma16816(float* d, const uint32_t* a, const uint32_t* b) {
    asm volatile(
        "mma.sync.aligned.m16n8k16.row.col.f32.bf16.bf16.f32 "
        "{%0,%1,%2,%3}, {%4,%5,%6,%7}, {%8,%9}, {%0,%1,%2,%3};"
        : "+f"(d[0]), "+f"(d[1]), "+f"(d[2]), "+f"(d[3])
        : "r"(a[0]), "r"(a[1]), "r"(a[2]), "r"(a[3]), "r"(b[0]), "r"(b[1]));
}

// smem map (bytes): sAh@0 (18432) sAl@18432 sBh@36864 (9216) sBl@46080; total 55296
__global__ void __launch_bounds__(256) tgemm_hl(
    int Asel, int Bsel, const float* __restrict__ bias1, const float* __restrict__ bias2,
    int Csel, int M, int N, int K, int mode)
{
    extern __shared__ __align__(16) char smraw[];
    float* stage = reinterpret_cast<float*>(smraw);

    const __nv_bfloat16 *Ah, *Al;
    if (Asel == 0)      { Ah = g_xh;  Al = g_xl;  }
    else if (Asel == 1) { Ah = g_h0h; Al = g_h0l; }
    else                { Ah = g_h1h; Al = g_h1l; }
    const __nv_bfloat16 *Bh_g, *Bl_g;
    if (Bsel == 0)      { Bh_g = g_w0h[0]; Bl_g = g_w0l[0]; }
    else if (Bsel == 1) { Bh_g = g_w0h[1]; Bl_g = g_w0l[1]; }
    else if (Bsel == 2) { Bh_g = g_w1h[0]; Bl_g = g_w1l[0]; }
    else if (Bsel == 3) { Bh_g = g_w1h[1]; Bl_g = g_w1l[1]; }
    else                { Bh_g = g_fch;    Bl_g = g_fcl;    }
    float* C = (Csel == 0) ? g_projF : ((Csel == 1) ? g_projB : g_logits);

    int tid = threadIdx.x;
    int lane = tid & 31;
    int w = tid >> 5;
    int wm = (w >> 1) * 32;
    int wn = (w & 1) * 32;
    int mB = blockIdx.y * 128, nB = blockIdx.x * 64;

    uint32_t smb = (uint32_t)__cvta_generic_to_shared(smraw);
    int a_row = (lane & 15);
    int a_col = (lane >> 4) << 3;
    int b_row = (lane & 7) + ((lane >> 4) << 3);
    int b_col = ((lane >> 3) & 1) << 3;

    float acc[2][4][4];
#pragma unroll
    for (int mt = 0; mt < 2; mt++)
#pragma unroll
        for (int nt = 0; nt < 4; nt++)
#pragma unroll
            for (int e = 0; e < 4; e++) acc[mt][nt][e] = 0.0f;

    for (int k0 = 0; k0 < K; k0 += 64) {
        __syncthreads();
#pragma unroll
        for (int e = 0; e < 4; e++) {
            int fid = tid + e * 256;
            int row = fid >> 3;
            int q = fid & 7;
            int so = (row * TPITCH + q * 8) * 2;
            *reinterpret_cast<uint4*>(smraw + so) =
                *(reinterpret_cast<const uint4*>(Ah + (size_t)(mB + row) * K + k0) + q);
            *reinterpret_cast<uint4*>(smraw + 18432 + so) =
                *(reinterpret_cast<const uint4*>(Al + (size_t)(mB + row) * K + k0) + q);
        }
#pragma unroll
        for (int e = 0; e < 2; e++) {
            int fid = tid + e * 256;
            int row = fid >> 3;
            int q = fid & 7;
            uint4 vh = make_uint4(0u, 0u, 0u, 0u), vl = make_uint4(0u, 0u, 0u, 0u);
            if (nB + row < N) {
                vh = *(reinterpret_cast<const uint4*>(Bh_g + (size_t)(nB + row) * K + k0) + q);
                vl = *(reinterpret_cast<const uint4*>(Bl_g + (size_t)(nB + row) * K + k0) + q);
            }
            int so = (row * TPITCH + q * 8) * 2;
            *reinterpret_cast<uint4*>(smraw + 36864 + so) = vh;
            *reinterpret_cast<uint4*>(smraw + 46080 + so) = vl;
        }
        __syncthreads();

#pragma unroll
        for (int kk = 0; kk < 64; kk += 16) {
            uint32_t Ah0[4], Ah1[4], Al0[4], Al1[4];
            uint32_t Bh[2][4], Bl[2][4];
            uint32_t a0 = smb + ((wm + a_row) * TPITCH + kk + a_col) * 2;
            ldmx4(Ah0[0], Ah0[1], Ah0[2], Ah0[3], a0);
            uint32_t a1 = smb + ((wm + 16 + a_row) * TPITCH + kk + a_col) * 2;
            ldmx4(Ah1[0], Ah1[1], Ah1[2], Ah1[3], a1);
            ldmx4(Al0[0], Al0[1], Al0[2], Al0[3], a0 + 18432);
            ldmx4(Al1[0], Al1[1], Al1[2], Al1[3], a1 + 18432);
#pragma unroll
            for (int p = 0; p < 2; p++) {
                uint32_t bo = smb + 36864 +
                    ((wn + p * 16 + b_row) * TPITCH + kk + b_col) * 2;
                ldmx4(Bh[p][0], Bh[p][1], Bh[p][2], Bh[p][3], bo);
                ldmx4(Bl[p][0], Bl[p][1], Bl[p][2], Bl[p][3], bo + 9216);
            }
#pragma unroll
            for (int nt = 0; nt < 4; nt++) {
                const uint32_t* bh = &Bh[nt >> 1][(nt & 1) * 2];
                const uint32_t* bl = &Bl[nt >> 1][(nt & 1) * 2];
                mma16816(acc[0][nt], Ah0, bh);
                mma16816(acc[1][nt], Ah1, bh);
                mma16816(acc[0][nt], Ah0, bl);
                mma16816(acc[1][nt], Ah1, bl);
                mma16816(acc[0][nt], Al0, bh);
                mma16816(acc[1][nt], Al1, bh);
            }
        }
    }

#pragma unroll
    for (int nt = 0; nt < 4; nt++) {
        int n0 = nB + wn + nt * 8 + (lane & 3) * 2;
        float bv0 = 0.f, bv1 = 0.f;
        if (n0 < N)     { bv0 = bias1[n0];     if (bias2) bv0 += bias2[n0]; }
        if (n0 + 1 < N) { bv1 = bias1[n0 + 1]; if (bias2) bv1 += bias2[n0 + 1]; }
#pragma unroll
        for (int mt = 0; mt < 2; mt++) {
            acc[mt][nt][0] += bv0; acc[mt][nt][1] += bv1;
            acc[mt][nt][2] += bv0; acc[mt][nt][3] += bv1;
        }
    }

    if (mode == 0) {
#pragma unroll
        for (int mt = 0; mt < 2; mt++)
#pragma unroll
            for (int nt = 0; nt < 4; nt++) {
                int m = mB + wm + mt * 16 + (lane >> 2);
                int n0 = nB + wn + nt * 8 + (lane & 3) * 2;
                if (n0 < N)     C[(size_t)m * N + n0]           = acc[mt][nt][0];
                if (n0 + 1 < N) C[(size_t)m * N + n0 + 1]       = acc[mt][nt][1];
                if (n0 < N)     C[(size_t)(m + 8) * N + n0]     = acc[mt][nt][2];
                if (n0 + 1 < N) C[(size_t)(m + 8) * N + n0 + 1] = acc[mt][nt][3];
            }
        return;
    }

    __syncthreads();
    float* st = stage + w * 1056;     // 32(nl) x 33(ml)
#pragma unroll
    for (int mt = 0; mt < 2; mt++)
#pragma unroll
        for (int nt = 0; nt < 4; nt++) {
            int ml = mt * 16 + (lane >> 2);
            int nl = nt * 8 + (lane & 3) * 2;
            st[nl * 33 + ml]           = acc[mt][nt][0];
            st[(nl + 1) * 33 + ml]     = acc[mt][nt][1];
            st[nl * 33 + ml + 8]       = acc[mt][nt][2];
            st[(nl + 1) * 33 + ml + 8] = acc[mt][nt][3];
        }
    __syncwarp();
#pragma unroll
    for (int i = 0; i < 8; i++) {
        int t2 = i >> 2;
        int nl = (i & 3) * 8 + (lane >> 2);
        int bq = lane & 3;
        float4 v;
        v.x = st[nl * 33 + t2 * 16 + bq * 4 + 0];
        v.y = st[nl * 33 + t2 * 16 + bq * 4 + 1];
        v.z = st[nl * 33 + t2 * 16 + bq * 4 + 2];
        v.w = st[nl * 33 + t2 * 16 + bq * 4 + 3];
        int t = (mB + wm) / 16 + t2;
        int gn = nB + wn + nl;
        *reinterpret_cast<float4*>(&C[((size_t)t * N + gn) * 16 + bq * 4]) = v;
    }
}

// ---------------- persistent bi-LSTM layer (exact R15 version: measured in the 15.56ms run) ----------------
__global__ void __launch_bounds__(256, 1) lstm_layer(int layer)
{
    extern __shared__ float smem[];
    float* hs   = smem;           // 12800 floats
    float* gsm  = smem + 12800;   // 1024
    float* red  = smem + 13824;   // 4096

    int bx = blockIdx.x;
    int dir = bx & 1, gblk = bx >> 1;
    int tid = threadIdx.x;
    const float* proj = dir ? g_projB : g_projF;
    const float* WT   = g_WT[layer * 2 + dir];
    float* hseq = layer ? g_h1 : g_h0;

    unsigned my_phase = 0;
    if (tid == 0) my_phase = ld_relaxed(&g_bar_phase);

    int ua = tid >> 4, b = tid & 15;
    int u  = gblk * 16 + ua;
    int w  = tid >> 5, lane = tid & 31;
    int ks = w & 3;
    int rh = w >> 2;
    int row_local = rh * 32 + lane;
    const float* Wk = WT + (size_t)(ks * 200) * 3200 + gblk * 64 + row_local;
    int rrow = tid >> 2, bq = tid & 3;
    int Rglob = (rrow >> 4) * 800 + gblk * 16 + (rrow & 15);

    const ulonglong2* hs2 = reinterpret_cast<const ulonglong2*>(hs);

    float c_reg = 0.0f;

    for (int s = 0; s <= 576; s++) {
        if (s > 0) {
            float gi = gsm[(0 * 16 + ua) * 16 + b];
            float gf = gsm[(16 + ua) * 16 + b];
            float gg = gsm[(32 + ua) * 16 + b];
            float go = gsm[(48 + ua) * 16 + b];
            float cn = fast_sig(gf) * c_reg + fast_sig(gi) * fast_tanh(gg);
            c_reg = cn;
            float h = fast_sig(go) * fast_tanh(cn);
            __stcg(&g_hbuf[(s - 1) & 1][dir][u * 16 + b], h);
            int tprev = dir ? (576 - s) : (s - 1);
            __stcg(&hseq[(size_t)(tprev * 16 + b) * 1600 + dir * 800 + u], h);
        }
        if (s == 576) break;

        __syncthreads();
        if (tid == 0) {
            my_phase++;
            unsigned a = atom_arrive_acqrel(&g_bar_count);
            if (a == NBLK - 1u) {
                st_relaxed(&g_bar_count, 0u);
                st_release(&g_bar_phase, my_phase);
            } else {
                while (ld_acquire(&g_bar_phase) != my_phase) { }
            }
        }
        __syncthreads();

        if (s == 0) {
            for (int e4 = tid; e4 < 3200; e4 += 256)
                reinterpret_cast<float4*>(hs)[e4] = make_float4(0.f, 0.f, 0.f, 0.f);
        } else {
            const float4* hb = reinterpret_cast<const float4*>(g_hbuf[(s - 1) & 1][dir]);
            for (int e4 = tid; e4 < 3200; e4 += 256)
                reinterpret_cast<float4*>(hs)[e4] = __ldcg(hb + e4);
        }
        __syncthreads();

        unsigned long long acc0 = 0ull, acc1 = 0ull, acc2 = 0ull, acc3 = 0ull;
        unsigned long long acc4 = 0ull, acc5 = 0ull, acc6 = 0ull, acc7 = 0ull;
        int kbase = ks * 200;
#pragma unroll 1
        for (int kk = 0; kk < 200; kk += 8) {
            float wv[8];
#pragma unroll
            for (int j = 0; j < 8; j++)
                wv[j] = __ldcg(Wk + (size_t)(kk + j) * 3200);
#pragma unroll
            for (int j = 0; j < 8; j++) {
                int k = kbase + kk + j;
                ulonglong2 hA = hs2[k * 4 + 0];
                ulonglong2 hB = hs2[k * 4 + 1];
                ulonglong2 hC = hs2[k * 4 + 2];
                ulonglong2 hD = hs2[k * 4 + 3];
                unsigned long long wp = bcast2(wv[j]);
                fma2(acc0, wp, hA.x); fma2(acc1, wp, hA.y);
                fma2(acc2, wp, hB.x); fma2(acc3, wp, hB.y);
                fma2(acc4, wp, hC.x); fma2(acc5, wp, hC.y);
                fma2(acc6, wp, hD.x); fma2(acc7, wp, hD.y);
            }
        }
        {
            float* dst = red + ks * 1024 + row_local * 16;
            float2 p0 = unpack2(acc0), p1 = unpack2(acc1);
            float2 p2 = unpack2(acc2), p3 = unpack2(acc3);
            float2 p4 = unpack2(acc4), p5 = unpack2(acc5);
            float2 p6 = unpack2(acc6), p7 = unpack2(acc7);
            *reinterpret_cast<float4*>(dst + 0)  = make_float4(p0.x, p0.y, p1.x, p1.y);
            *reinterpret_cast<float4*>(dst + 4)  = make_float4(p2.x, p2.y, p3.x, p3.y);
            *reinterpret_cast<float4*>(dst + 8)  = make_float4(p4.x, p4.y, p5.x, p5.y);
            *reinterpret_cast<float4*>(dst + 12) = make_float4(p6.x, p6.y, p7.x, p7.y);
        }
        __syncthreads();
        {
            int t = dir ? (575 - s) : s;
            float4 pv = __ldcg(reinterpret_cast<const float4*>(
                            proj + ((size_t)t * 3200 + Rglob) * 16 + bq * 4));
            int off = rrow * 16 + bq * 4;
            float4 s0 = *reinterpret_cast<const float4*>(red + 0 * 1024 + off);
            float4 s1 = *reinterpret_cast<const float4*>(red + 1 * 1024 + off);
            float4 s2 = *reinterpret_cast<const float4*>(red + 2 * 1024 + off);
            float4 s3 = *reinterpret_cast<const float4*>(red + 3 * 1024 + off);
            float4 rv;
            rv.x = pv.x + ((s0.x + s1.x) + (s2.x + s3.x));
            rv.y = pv.y + ((s0.y + s1.y) + (s2.y + s3.y));
            rv.z = pv.z + ((s0.z + s1.z) + (s2.z + s3.z));
            rv.w = pv.w + ((s0.w + s1.w) + (s2.w + s3.w));
            *reinterpret_cast<float4*>(gsm + off) = rv;
        }
        __syncthreads();
    }
}

// ---------------- softmax + angle mixing + SRF ----------------
__global__ void phisrf(const float* __restrict__ alphabet,
                       const float* __restrict__ blen, const float* __restrict__ bang) {
    __shared__ float sA[180], cA[180];
    int tid = threadIdx.x;
    if (tid < 180) { float a = alphabet[tid]; sA[tid] = sinf(a); cA[tid] = cosf(a); }
    __syncthreads();
    int row = blockIdx.x * 256 + tid;
    if (row >= NROW) return;
    const float* z = g_logits + (size_t)row * 60;
    float mx = -1e30f;
    for (int j = 0; j < 60; j++) mx = fmaxf(mx, z[j]);
    float ss0 = 0, ss1 = 0, ss2 = 0, sc0 = 0, sc1 = 0, sc2 = 0;
    for (int j = 0; j < 60; j++) {
        float e = __expf(z[j] - mx);
        ss0 += e * sA[j * 3 + 0]; sc0 += e * cA[j * 3 + 0];
        ss1 += e * sA[j * 3 + 1]; sc1 += e * cA[j * 3 + 1];
        ss2 += e * sA[j * 3 + 2]; sc2 += e * cA[j * 3 + 2];
    }
    float ss[3] = {ss0, ss1, ss2}, sc[3] = {sc0, sc1, sc2};
    int l = row >> 4, b = row & 15;
#pragma unroll
    for (int d = 0; d < 3; d++) {
        float rh = rsqrtf(ss[d] * ss[d] + sc[d] * sc[d]);
        float cp = sc[d] * rh, sp = ss[d] * rh;
        float rr = blen[d], th = bang[d];
        float sth = sinf(th), cth = cosf(th);
        float* o = &g_srf[(((size_t)(3 * l + d)) * 16 + b) * 3];
        o[0] = rr * cth;
        o[1] = rr * cp * sth;
        o[2] = rr * sp * sth;
    }
}

// ---------------- pNeRF ----------------
struct F3 { float x, y, z; };
__device__ __forceinline__ F3 mk3(float x, float y, float z) { F3 r; r.x = x; r.y = y; r.z = z; return r; }
__device__ __forceinline__ F3 sub3(F3 a, F3 b) { return mk3(a.x - b.x, a.y - b.y, a.z - b.z); }
__device__ __forceinline__ F3 crs3(F3 a, F3 b) {
    return mk3(a.y * b.z - a.z * b.y, a.z * b.x - a.x * b.z, a.x * b.y - a.y * b.x);
}
__device__ __forceinline__ F3 unit3(F3 v) {
    float r = rsqrtf(v.x * v.x + v.y * v.y + v.z * v.z);
    return mk3(v.x * r, v.y * r, v.z * r);
}

__global__ void pnerf_kernel(float* __restrict__ out) {
    __shared__ float Rm[16][9];
    __shared__ float Og[16][3];
    int tid = threadIdx.x;
    {
        int kf = tid >> 4, b = tid & 15;
        F3 A  = mk3(-0.70710678118654752f, 1.22474487139158905f, 0.f);
        F3 Bp = mk3(-1.41421356237309505f, 0.f, 0.f);
        F3 C  = mk3(0.f, 0.f, 0.f);
        for (int f = 0; f < 72; f++) {
            const float* ct = &g_srf[(((size_t)(kf * 72 + f)) * 16 + b) * 3];
            F3 bc = unit3(sub3(C, Bp));
            F3 n  = unit3(crs3(sub3(Bp, A), bc));
            F3 m  = crs3(n, bc);
            F3 D  = mk3(C.x + bc.x * ct[0] + m.x * ct[1] + n.x * ct[2],
                        C.y + bc.y * ct[0] + m.y * ct[1] + n.y * ct[2],
                        C.z + bc.z * ct[0] + m.z * ct[1] + n.z * ct[2]);
            float* fp = &g_frag[((((size_t)f) * 24 + kf) * 16 + b) * 3];
            fp[0] = D.x; fp[1] = D.y; fp[2] = D.z;
            A = Bp; Bp = C; C = D;
        }
    }
    __syncthreads();
    for (int e = tid; e < 72 * 16; e += 384) {
        int f = e >> 4, b = e & 15;
        const float* fp = &g_frag[((((size_t)f) * 24 + 0) * 16 + b) * 3];
        float* o = &out[((size_t)f * 16 + b) * 3];
        o[0] = fp[0]; o[1] = fp[1]; o[2] = fp[2];
    }
    __syncthreads();
    for (int k = 1; k < 24; k++) {
        if (tid < 16) {
            int base = 72 * k;
            const float* pa = &out[((size_t)(base - 3) * 16 + tid) * 3];
            const float* pb = &out[((size_t)(base - 2) * 16 + tid) * 3];
            const float* pc = &out[((size_t)(base - 1) * 16 + tid) * 3];
            F3 A  = mk3(pa[0], pa[1], pa[2]);
            F3 B2 = mk3(pb[0], pb[1], pb[2]);
            F3 C  = mk3(pc[0], pc[1], pc[2]);
            F3 bc = unit3(sub3(C, B2));
            F3 n  = unit3(crs3(sub3(B2, A), bc));
            F3 m  = crs3(n, bc);
            Rm[tid][0] = bc.x; Rm[tid][1] = bc.y; Rm[tid][2] = bc.z;
            Rm[tid][3] = m.x;  Rm[tid][4] = m.y;  Rm[tid][5] = m.z;
            Rm[tid][6] = n.x;  Rm[tid][7] = n.y;  Rm[tid][8] = n.z;
            Og[tid][0] = C.x;  Og[tid][1] = C.y;  Og[tid][2] = C.z;
        }
        __syncthreads();
        for (int e = tid; e < 72 * 16; e += 384) {
            int f = e >> 4, b = e & 15;
            const float* fp = &g_frag[((((size_t)f) * 24 + k) * 16 + b) * 3];
            float vx = fp[0], vy = fp[1], vz = fp[2];
            float* o = &out[((size_t)(72 * k + f) * 16 + b) * 3];
            o[0] = Og[b][0] + Rm[b][0] * vx + Rm[b][3] * vy + Rm[b][6] * vz;
            o[1] = Og[b][1] + Rm[b][1] * vx + Rm[b][4] * vy + Rm[b][7] * vz;
            o[2] = Og[b][2] + Rm[b][2] * vx + Rm[b][5] * vy + Rm[b][8] * vz;
        }
        __syncthreads();
    }
}

// ---------------- launch ----------------
extern "C" void kernel_launch(void* const* d_in, const int* in_sizes, int n_in,
                              void* d_out, int out_size) {
    const int*   seq      = (const int*)  d_in[0];
    const float* pssm     = (const float*)d_in[1];
    const float* w_ih_l0f = (const float*)d_in[3];
    const float* w_hh_l0f = (const float*)d_in[4];
    const float* b_ih_l0f = (const float*)d_in[5];
    const float* b_hh_l0f = (const float*)d_in[6];
    const float* w_ih_l0b = (const float*)d_in[7];
    const float* w_hh_l0b = (const float*)d_in[8];
    const float* b_ih_l0b = (const float*)d_in[9];
    const float* b_hh_l0b = (const float*)d_in[10];
    const float* w_ih_l1f = (const float*)d_in[11];
    const float* w_hh_l1f = (const float*)d_in[12];
    const float* b_ih_l1f = (const float*)d_in[13];
    const float* b_hh_l1f = (const float*)d_in[14];
    const float* w_ih_l1b = (const float*)d_in[15];
    const float* w_hh_l1b = (const float*)d_in[16];
    const float* b_ih_l1b = (const float*)d_in[17];
    const float* b_hh_l1b = (const float*)d_in[18];
    const float* fc_w     = (const float*)d_in[19];
    const float* fc_b     = (const float*)d_in[20];
    const float* alphabet = (const float*)d_in[21];
    const float* blen     = (const float*)d_in[22];
    const float* bang     = (const float*)d_in[23];
    float* out = (float*)d_out;

    cudaFuncSetAttribute((const void*)lstm_layer,
                         cudaFuncAttributeMaxDynamicSharedMemorySize, 71680);
    cudaFuncSetAttribute((const void*)tgemm_hl,
                         cudaFuncAttributeMaxDynamicSharedMemorySize, 55296);

    // input prep (independent of LSTM outputs)
    build_x_hl<<<(NROW * 64 + 255) / 256, 256>>>(seq, pssm);
    pad_split_w0<<<(2 * 3200 * 64 + 255) / 256, 256>>>(w_ih_l0f, w_ih_l0b);
    split_sel<<<5000, 256>>>(2, w_ih_l1f, 3200 * 1600 / 4);
    split_sel<<<5000, 256>>>(3, w_ih_l1b, 3200 * 1600 / 4);
    split_sel<<<94, 256>>>(4, fc_w, 60 * 1600 / 4);
    transpose_whh<<<8192, 256>>>(w_hh_l0f, w_hh_l0b, w_hh_l1f, w_hh_l1b);

    // layer 0 projections (K padded to 64), tensor cores
    dim3 gT(50, 72);
    tgemm_hl<<<gT, 256, 55296>>>(0, 0, b_ih_l0f, b_hh_l0f, 0, NROW, 3200, 64, 1);
    tgemm_hl<<<gT, 256, 55296>>>(0, 1, b_ih_l0b, b_hh_l0b, 1, NROW, 3200, 64, 1);
    lstm_layer<<<NBLK, 256, 71680>>>(0);

    // split h0, then layer 1 projections (K=1600)
    split_sel<<<14400, 256>>>(0, nullptr, NROW * 1600 / 4);
    tgemm_hl<<<gT, 256, 55296>>>(1, 2, b_ih_l1f, b_hh_l1f, 0, NROW, 3200, 1600, 1);
    tgemm_hl<<<gT, 256, 55296>>>(1, 3, b_ih_l1b, b_hh_l1b, 1, NROW, 3200, 1600, 1);
    lstm_layer<<<NBLK, 256, 71680>>>(1);

    // split h1, FC -> logits
    split_sel<<<14400, 256>>>(1, nullptr, NROW * 1600 / 4);
    tgemm_hl<<<dim3(1, 72), 256, 55296>>>(2, 4, fc_b, nullptr, 2, NROW, 60, 1600, 0);

    phisrf<<<36, 256>>>(alphabet, blen, bang);
    pnerf_kernel<<<1, 384>>>(out);
}